// round 16
// baseline (speedup 1.0000x reference)
#include <cuda_runtime.h>
#include <cuda_fp16.h>
#include <math.h>
#include <cstdint>

#define BB 32
#define TT 2048
#define HH 1024

// Scratch (allocation-free rule: __device__ globals)
__device__ float g_decfea[BB * HH];
__device__ float g_scores[BB * TT];
__device__ __half g_B[(size_t)HH * HH];            // W_prev fp16 (2 MB)
__device__ __half g_A[(size_t)BB * TT * HH];       // prev_s fp16 (134 MB)

// ---------------------------------------------------------------------------
// PTX helpers
// ---------------------------------------------------------------------------
__device__ __forceinline__ uint32_t smem_u32(const void* p) {
    uint32_t a;
    asm("{ .reg .u64 t; cvta.to.shared.u64 t, %1; cvt.u32.u64 %0, t; }" : "=r"(a) : "l"(p));
    return a;
}
__device__ __forceinline__ void cp_async16(uint32_t dst, const void* src) {
    asm volatile("cp.async.cg.shared.global [%0], [%1], 16;" :: "r"(dst), "l"(src) : "memory");
}
__device__ __forceinline__ void cp_commit() {
    asm volatile("cp.async.commit_group;" ::: "memory");
}
template <int N>
__device__ __forceinline__ void cp_wait() {
    asm volatile("cp.async.wait_group %0;" :: "n"(N) : "memory");
}
__device__ __forceinline__ void ldsm_x4(uint32_t addr, uint32_t& r0, uint32_t& r1,
                                        uint32_t& r2, uint32_t& r3) {
    asm volatile("ldmatrix.sync.aligned.m8n8.x4.shared.b16 {%0,%1,%2,%3}, [%4];"
                 : "=r"(r0), "=r"(r1), "=r"(r2), "=r"(r3) : "r"(addr));
}
__device__ __forceinline__ void mma_f32(float* c, const uint32_t* a, const uint32_t* b) {
    asm volatile(
        "mma.sync.aligned.m16n8k16.row.col.f32.f16.f16.f32 "
        "{%0,%1,%2,%3}, {%4,%5,%6,%7}, {%8,%9}, {%0,%1,%2,%3};"
        : "+f"(c[0]), "+f"(c[1]), "+f"(c[2]), "+f"(c[3])
        : "r"(a[0]), "r"(a[1]), "r"(a[2]), "r"(a[3]), "r"(b[0]), "r"(b[1]));
}
__device__ __forceinline__ float fast_tanh(float x) {
    float y;
    asm("tanh.approx.f32 %0, %1;" : "=f"(y) : "f"(x));
    return y;
}
__device__ __forceinline__ uint32_t pack_h2(__half a, __half b) {
    __half2 t = __halves2half2(a, b);
    return *reinterpret_cast<uint32_t*>(&t);
}

// ---------------------------------------------------------------------------
// Prologue kernel: blocks 0..511 = conv_b (W_prev->fp16), 512..575 = init
// (zero ct + s_t concat row), 576..703 = dec_fea.
// ---------------------------------------------------------------------------
__global__ void prologue_kernel(const float* __restrict__ W_prev,
                                __half* __restrict__ gB,
                                const float* __restrict__ s_t,
                                const float* __restrict__ W_s,
                                const float* __restrict__ b_s,
                                float* __restrict__ out) {
    const int blk = blockIdx.x;
    const int tid = threadIdx.x;
    if (blk < 512) {
        size_t t = (size_t)blk * 256 + tid;
        const float* s = W_prev + t * 8;
        float4 f0 = *(const float4*)s;
        float4 f1 = *(const float4*)(s + 4);
        uint4 o;
        o.x = pack_h2(__float2half_rn(f0.x), __float2half_rn(f0.y));
        o.y = pack_h2(__float2half_rn(f0.z), __float2half_rn(f0.w));
        o.z = pack_h2(__float2half_rn(f1.x), __float2half_rn(f1.y));
        o.w = pack_h2(__float2half_rn(f1.z), __float2half_rn(f1.w));
        *(uint4*)(gB + t * 8) = o;
    } else if (blk < 576) {
        int idx = (blk - 512) * 256 + tid;   // 0..16383 float4 units
        if (idx < 8192) {
            reinterpret_cast<float4*>(out)[idx] = make_float4(0.f, 0.f, 0.f, 0.f);
        } else {
            int i = idx - 8192;
            int b = i >> 8, c = i & 255;
            float4 sv = reinterpret_cast<const float4*>(s_t + (size_t)b * HH)[c];
            float* pn = out + BB * HH + ((size_t)b * (TT + 1) + TT) * HH;
            reinterpret_cast<float4*>(pn)[c] = sv;
        }
    } else {
        const int b = tid & 31;
        const int d = (blk - 576) * 8 + (tid >> 5);
        const float4* __restrict__ wrow =
            reinterpret_cast<const float4*>(W_s + (size_t)d * HH);
        const float4* __restrict__ srow =
            reinterpret_cast<const float4*>(s_t + (size_t)b * HH);
        float acc = 0.f;
#pragma unroll 8
        for (int k = 0; k < 256; k++) {
            float4 w = wrow[k];
            float4 s = srow[k];
            acc += w.x * s.x + w.y * s.y + w.z * s.z + w.w * s.w;
        }
        g_decfea[b * HH + d] = acc + __ldg(&b_s[d]);
    }
}

// ---------------------------------------------------------------------------
// A prepack only (plain fp16).
// ---------------------------------------------------------------------------
__global__ void conv_half_kernel(const float* __restrict__ src,
                                 __half* __restrict__ dst) {
    size_t t = (size_t)blockIdx.x * 256 + threadIdx.x;  // x8 elems
    size_t e = t * 8;
    float4 f0 = *(const float4*)(src + e);
    float4 f1 = *(const float4*)(src + e + 4);
    uint4 o;
    o.x = pack_h2(__float2half_rn(f0.x), __float2half_rn(f0.y));
    o.y = pack_h2(__float2half_rn(f0.z), __float2half_rn(f0.w));
    o.z = pack_h2(__float2half_rn(f1.x), __float2half_rn(f1.y));
    o.w = pack_h2(__float2half_rn(f1.z), __float2half_rn(f1.w));
    *(uint4*)(dst + e) = o;
}

// ---------------------------------------------------------------------------
// Kernel 2: fused score GEMM + EMBEDDED concat copy.
// CTA: 64 M x (8 n-chunks of 128), 4-stage cp.async ring, 1 barrier/slab.
// 8 warps = 2(m) x 4(n); warp tile 32m x 32n; 2 CTAs/SM.
// Per nc-iteration each warp copies one prev_s row to out (8 rows/CTA/nc,
// 64 rows total) — drains in score's idle DRAM window (~5% busy).
// ---------------------------------------------------------------------------
constexpr int A_PLANE = 5120;       // 64 rows * 80B
constexpr int B_PLANE = 10240;      // 128 rows * 80B
constexpr int STAGE = A_PLANE + B_PLANE;       // 15360
constexpr int NSTAGE = 4;
constexpr int V_OFF = STAGE * NSTAGE;          // 61440
constexpr int DEC_OFF = V_OFF + 4096;
constexpr int RED_OFF = DEC_OFF + 4096;
constexpr int SMEM_BYTES = RED_OFF + 4096;     // 73728

__device__ __forceinline__ void fill_slab(uint32_t sb, int st, int s,
                                          int row0, int n0, int tid) {
#pragma unroll
    for (int it = 0; it < 3; it++) {
        int idx = tid + it * 256;           // 0..767
        if (idx < 256) {
            int m = idx >> 2;
            int c = idx & 3;
            const __half* src = g_A + (size_t)(row0 + m) * HH + s * 32 + c * 8;
            uint32_t dst = sb + (uint32_t)(st * STAGE) + m * 80 + c * 16;
            cp_async16(dst, src);
        } else {
            int loc = idx - 256;
            int m = loc >> 2;
            int c = loc & 3;
            const __half* src = g_B + (size_t)(n0 + m) * HH + s * 32 + c * 8;
            uint32_t dst = sb + (uint32_t)(st * STAGE) + A_PLANE + m * 80 + c * 16;
            cp_async16(dst, src);
        }
    }
}

__global__ void __launch_bounds__(256, 2)
score_kernel(const float* __restrict__ vvec,
             const float* __restrict__ prev_s,
             float* __restrict__ out) {
    extern __shared__ char smem[];
    const uint32_t sb = smem_u32(smem);
    const int tid = threadIdx.x;
    const int warp = tid >> 5;
    const int lane = tid & 31;
    const int wm = warp >> 2;   // 0..1
    const int wn = warp & 3;    // 0..3
    const int row0 = blockIdx.x * 64;
    const int b = blockIdx.x >> 5;    // 32 CTAs per batch
    const int tt0 = (blockIdx.x & 31) * 64;  // row-in-batch base

    float* v_s = (float*)(smem + V_OFF);
    float* dec_s = (float*)(smem + DEC_OFF);
    for (int i = tid; i < 1024; i += 256) {
        v_s[i] = vvec[i];
        dec_s[i] = g_decfea[b * 1024 + i];
    }
    __syncthreads();

    const int a_row = wm * 32 + (lane & 15);                    // + mt*16
    const int a_col = ((lane >> 4) << 4);                       // 0 or 16 bytes
    const int b_row = wn * 32 + (((lane >> 4) & 1) << 3) + (lane & 7);  // + q*16
    const int b_col = (((lane >> 3) & 1) << 4);

    float msum[4];
#pragma unroll
    for (int i = 0; i < 4; i++) msum[i] = 0.f;

#pragma unroll 1
    for (int nc = 0; nc < 8; nc++) {
        const int n0 = nc * 128;
        float acc[2][4][4];
#pragma unroll
        for (int mt = 0; mt < 2; mt++)
#pragma unroll
            for (int nt = 0; nt < 4; nt++)
#pragma unroll
                for (int c = 0; c < 4; c++) acc[mt][nt][c] = 0.f;

        fill_slab(sb, 0, 0, row0, n0, tid);
        cp_commit();
        fill_slab(sb, 1, 1, row0, n0, tid);
        cp_commit();
        fill_slab(sb, 2, 2, row0, n0, tid);
        cp_commit();

        int st = 0;
#pragma unroll 1
        for (int s = 0; s < 32; s++) {
            if (s <= 29) {
                cp_wait<2>();
            } else if (s == 30) {
                cp_wait<1>();
            } else {
                cp_wait<0>();
            }
            __syncthreads();  // single barrier per slab

            if (s < 29) {
                fill_slab(sb, (st + 3) & 3, s + 3, row0, n0, tid);
                cp_commit();
            }

            const uint32_t abase = sb + (uint32_t)(st * STAGE);
            const uint32_t bbase = abase + (uint32_t)A_PLANE;
#pragma unroll
            for (int ks = 0; ks < 2; ks++) {
                uint32_t ah[2][4];
#pragma unroll
                for (int mt = 0; mt < 2; mt++) {
                    uint32_t ra = abase + (a_row + mt * 16) * 80 + a_col + ks * 32;
                    ldsm_x4(ra, ah[mt][0], ah[mt][1], ah[mt][2], ah[mt][3]);
                }
#pragma unroll
                for (int q = 0; q < 2; q++) {
                    uint32_t bm[2][2];
                    {
                        uint32_t rb = bbase + (b_row + q * 16) * 80 + b_col + ks * 32;
                        uint32_t r0, r1, r2, r3;
                        ldsm_x4(rb, r0, r1, r2, r3);
                        bm[0][0] = r0; bm[0][1] = r1;
                        bm[1][0] = r2; bm[1][1] = r3;
                    }
#pragma unroll
                    for (int mt = 0; mt < 2; mt++)
#pragma unroll
                        for (int j = 0; j < 2; j++)
                            mma_f32(acc[mt][2 * q + j], ah[mt], bm[j]);
                }
            }
            st = (st + 1) & 3;
        }

        // Embedded concat copy: this warp copies prev_s row (row0+nc*8+warp)
        // to out. Loads issue here; stores after the tanh block below so the
        // LDG latency hides behind the epilogue math.
        float4 cp[8];
        {
            const float4* srcr = reinterpret_cast<const float4*>(
                prev_s + (size_t)(row0 + nc * 8 + warp) * HH);
#pragma unroll
            for (int i = 0; i < 8; i++) cp[i] = srcr[lane + i * 32];
        }

        // Epilogue: msum += v[d]*tanh(acc + dec[d])
#pragma unroll
        for (int nt = 0; nt < 4; nt++) {
#pragma unroll
            for (int j = 0; j < 2; j++) {
                int d = n0 + wn * 32 + nt * 8 + 2 * (lane & 3) + j;
                float vd = v_s[d];
                float dj = dec_s[d];
#pragma unroll
                for (int mt = 0; mt < 2; mt++) {
#pragma unroll
                    for (int h = 0; h < 2; h++) {
                        float x = acc[mt][nt][h * 2 + j] + dj;
                        msum[mt * 2 + h] += vd * fast_tanh(x);
                    }
                }
            }
        }

        {
            float4* dstr = reinterpret_cast<float4*>(
                out + (size_t)BB * HH +
                ((size_t)b * (TT + 1) + tt0 + nc * 8 + warp) * HH);
#pragma unroll
            for (int i = 0; i < 8; i++) dstr[lane + i * 32] = cp[i];
        }
    }

    // Cross-warp reduction (64 rows x 16 partials)
    float* red = (float*)(smem + RED_OFF);
    __syncthreads();
#pragma unroll
    for (int mt = 0; mt < 2; mt++)
#pragma unroll
        for (int h = 0; h < 2; h++) {
            int m = wm * 32 + mt * 16 + h * 8 + (lane >> 2);
            red[m * 16 + wn * 4 + (lane & 3)] = msum[mt * 2 + h];
        }
    __syncthreads();
    if (tid < 64) {
        float sum = 0.f;
#pragma unroll
        for (int x = 0; x < 16; x++) sum += red[tid * 16 + x];
        g_scores[row0 + tid] = sum;
    }
}

// ---------------------------------------------------------------------------
// ct kernel with FUSED softmax, reading fp16 g_A.
// ---------------------------------------------------------------------------
__global__ void ct_softmax_kernel(float* __restrict__ out) {
    const int b = blockIdx.y;
    const int chunk = blockIdx.x;   // 0..15
    const int tid = threadIdx.x;    // 256
    __shared__ float sred[256];
    __shared__ float w_s[128];

    const float* sc = g_scores + b * TT;

    float vals[8];
    float mx = -INFINITY;
#pragma unroll
    for (int i = 0; i < 8; i++) {
        vals[i] = sc[tid + i * 256];
        mx = fmaxf(mx, vals[i]);
    }
    sred[tid] = mx;
    __syncthreads();
    for (int s = 128; s > 0; s >>= 1) {
        if (tid < s) sred[tid] = fmaxf(sred[tid], sred[tid + s]);
        __syncthreads();
    }
    mx = sred[0];
    __syncthreads();
    float sum = 0.f;
#pragma unroll
    for (int i = 0; i < 8; i++) sum += __expf(vals[i] - mx);
    sred[tid] = sum;
    __syncthreads();
    for (int s = 128; s > 0; s >>= 1) {
        if (tid < s) sred[tid] += sred[tid + s];
        __syncthreads();
    }
    const float inv = 1.0f / sred[0];

    const int t0 = chunk * 128;
    if (tid < 128) w_s[tid] = __expf(sc[t0 + tid] - mx) * inv;
    __syncthreads();

    const uint2* src =
        reinterpret_cast<const uint2*>(g_A + ((size_t)b * TT + t0) * HH);
    float acc[4] = {0.f, 0.f, 0.f, 0.f};
#pragma unroll 4
    for (int t = 0; t < 128; t++) {
        uint2 p = src[(size_t)t * 256 + tid];
        float at = w_s[t];
        float2 f0 = __half22float2(*reinterpret_cast<__half2*>(&p.x));
        float2 f1 = __half22float2(*reinterpret_cast<__half2*>(&p.y));
        acc[0] += at * f0.x;
        acc[1] += at * f0.y;
        acc[2] += at * f1.x;
        acc[3] += at * f1.y;
    }
    float* ctb = out + (size_t)b * HH + tid * 4;
    atomicAdd(ctb + 0, acc[0]);
    atomicAdd(ctb + 1, acc[1]);
    atomicAdd(ctb + 2, acc[2]);
    atomicAdd(ctb + 3, acc[3]);
}

// ---------------------------------------------------------------------------
extern "C" void kernel_launch(void* const* d_in, const int* in_sizes, int n_in,
                              void* d_out, int out_size) {
    const float* s_t    = (const float*)d_in[0];
    const float* prev_s = (const float*)d_in[1];
    const float* W_prev = (const float*)d_in[2];
    const float* W_s    = (const float*)d_in[3];
    const float* b_s    = (const float*)d_in[4];
    const float* v      = (const float*)d_in[5];
    float* out = (float*)d_out;

    static bool once = false;
    if (!once) {
        cudaFuncSetAttribute(score_kernel,
                             cudaFuncAttributeMaxDynamicSharedMemorySize, SMEM_BYTES);
        once = true;
    }

    __half *gA, *gB;
    cudaGetSymbolAddress((void**)&gA, g_A);
    cudaGetSymbolAddress((void**)&gB, g_B);

    prologue_kernel<<<704, 256>>>(W_prev, gB, s_t, W_s, b_s, out);
    conv_half_kernel<<<32768, 256>>>(prev_s, gA);
    score_kernel<<<(BB * TT) / 64, 256, SMEM_BYTES>>>(v, prev_s, out);
    dim3 gt(16, BB);
    ct_softmax_kernel<<<gt, 256>>>(out);
}

// round 17
// speedup vs baseline: 1.0398x; 1.0398x over previous
#include <cuda_runtime.h>
#include <cuda_fp16.h>
#include <math.h>
#include <cstdint>

#define BB 32
#define TT 2048
#define HH 1024

// Scratch (allocation-free rule: __device__ globals)
__device__ float g_decfea[BB * HH];
__device__ float g_scores[BB * TT];
__device__ __half g_B[(size_t)HH * HH];            // W_prev fp16 (2 MB)
__device__ __half g_A[(size_t)BB * TT * HH];       // prev_s fp16 (134 MB)

// ---------------------------------------------------------------------------
// PTX helpers
// ---------------------------------------------------------------------------
__device__ __forceinline__ uint32_t smem_u32(const void* p) {
    uint32_t a;
    asm("{ .reg .u64 t; cvta.to.shared.u64 t, %1; cvt.u32.u64 %0, t; }" : "=r"(a) : "l"(p));
    return a;
}
__device__ __forceinline__ void cp_async16(uint32_t dst, const void* src) {
    asm volatile("cp.async.cg.shared.global [%0], [%1], 16;" :: "r"(dst), "l"(src) : "memory");
}
__device__ __forceinline__ void cp_commit() {
    asm volatile("cp.async.commit_group;" ::: "memory");
}
template <int N>
__device__ __forceinline__ void cp_wait() {
    asm volatile("cp.async.wait_group %0;" :: "n"(N) : "memory");
}
__device__ __forceinline__ void ldsm_x4(uint32_t addr, uint32_t& r0, uint32_t& r1,
                                        uint32_t& r2, uint32_t& r3) {
    asm volatile("ldmatrix.sync.aligned.m8n8.x4.shared.b16 {%0,%1,%2,%3}, [%4];"
                 : "=r"(r0), "=r"(r1), "=r"(r2), "=r"(r3) : "r"(addr));
}
__device__ __forceinline__ void mma_f32(float* c, const uint32_t* a, const uint32_t* b) {
    asm volatile(
        "mma.sync.aligned.m16n8k16.row.col.f32.f16.f16.f32 "
        "{%0,%1,%2,%3}, {%4,%5,%6,%7}, {%8,%9}, {%0,%1,%2,%3};"
        : "+f"(c[0]), "+f"(c[1]), "+f"(c[2]), "+f"(c[3])
        : "r"(a[0]), "r"(a[1]), "r"(a[2]), "r"(a[3]), "r"(b[0]), "r"(b[1]));
}
__device__ __forceinline__ float fast_tanh(float x) {
    float y;
    asm("tanh.approx.f32 %0, %1;" : "=f"(y) : "f"(x));
    return y;
}
__device__ __forceinline__ uint32_t pack_h2(__half a, __half b) {
    __half2 t = __halves2half2(a, b);
    return *reinterpret_cast<uint32_t*>(&t);
}

// ---------------------------------------------------------------------------
// A prepack (plain fp16) + concat copy fused (R13 known-good).
// ---------------------------------------------------------------------------
__global__ void conv_half_copy_kernel(const float* __restrict__ src,
                                      __half* __restrict__ dst,
                                      float* __restrict__ out) {
    size_t t = (size_t)blockIdx.x * 256 + threadIdx.x;  // x8 elems
    size_t e = t * 8;
    size_t row = e >> 10;               // b*2048 + tt
    int off = (int)(e & 1023);
    int b = (int)(row >> 11);
    int tt = (int)(row & 2047);

    float4 f0 = *(const float4*)(src + e);
    float4 f1 = *(const float4*)(src + e + 4);
    uint4 o;
    o.x = pack_h2(__float2half_rn(f0.x), __float2half_rn(f0.y));
    o.y = pack_h2(__float2half_rn(f0.z), __float2half_rn(f0.w));
    o.z = pack_h2(__float2half_rn(f1.x), __float2half_rn(f1.y));
    o.w = pack_h2(__float2half_rn(f1.z), __float2half_rn(f1.w));
    *(uint4*)(dst + e) = o;

    float* op = out + (size_t)BB * HH + ((size_t)b * (TT + 1) + tt) * HH + off;
    *(float4*)op = f0;
    *(float4*)(op + 4) = f1;
}

// B prepack: plain fp32 -> fp16
__global__ void conv_b_kernel(const float* __restrict__ src,
                              __half* __restrict__ dst) {
    size_t t = (size_t)blockIdx.x * 256 + threadIdx.x;  // x8 elems
    const float* s = src + t * 8;
    float4 f0 = *(const float4*)s;
    float4 f1 = *(const float4*)(s + 4);
    uint4 o;
    o.x = pack_h2(__float2half_rn(f0.x), __float2half_rn(f0.y));
    o.y = pack_h2(__float2half_rn(f0.z), __float2half_rn(f0.w));
    o.z = pack_h2(__float2half_rn(f1.x), __float2half_rn(f1.y));
    o.w = pack_h2(__float2half_rn(f1.z), __float2half_rn(f1.w));
    *(uint4*)(dst + t * 8) = o;
}

// ---------------------------------------------------------------------------
// Init kernel: zero ct_d region + write the s_t concat row.
// ---------------------------------------------------------------------------
__global__ void init_kernel(const float* __restrict__ s_t,
                            float* __restrict__ out) {
    int idx = blockIdx.x * 256 + threadIdx.x;   // 0..16383 (float4 units)
    if (idx < 8192) {
        reinterpret_cast<float4*>(out)[idx] = make_float4(0.f, 0.f, 0.f, 0.f);
    } else {
        int i = idx - 8192;                      // 0..8191 = b*256 + c
        int b = i >> 8, c = i & 255;
        float4 sv = reinterpret_cast<const float4*>(s_t + (size_t)b * HH)[c];
        float* pn = out + BB * HH + ((size_t)b * (TT + 1) + TT) * HH;
        reinterpret_cast<float4*>(pn)[c] = sv;
    }
}

// ---------------------------------------------------------------------------
// Kernel 1: dec_fea[b,d] = sum_h s_t[b,h] * W_s[d,h] + b_s[d]
// ---------------------------------------------------------------------------
__global__ void dec_fea_kernel(const float* __restrict__ s_t,
                               const float* __restrict__ W_s,
                               const float* __restrict__ b_s) {
    const int tid = threadIdx.x;
    const int b = tid & 31;
    const int d = blockIdx.x * 8 + (tid >> 5);
    const float4* __restrict__ wrow =
        reinterpret_cast<const float4*>(W_s + (size_t)d * HH);
    const float4* __restrict__ srow =
        reinterpret_cast<const float4*>(s_t + (size_t)b * HH);
    float acc = 0.f;
#pragma unroll 8
    for (int k = 0; k < 256; k++) {
        float4 w = wrow[k];
        float4 s = srow[k];
        acc += w.x * s.x + w.y * s.y + w.z * s.z + w.w * s.w;
    }
    g_decfea[b * HH + d] = acc + __ldg(&b_s[d]);
}

// ---------------------------------------------------------------------------
// Kernel 2: fused score GEMM, plain-fp16 mma.sync, f32 acc (R13 known-good).
// CTA: 64 M x (8 n-chunks of 128), 4-stage cp.async ring, 1 barrier/slab.
// 8 warps = 2(m) x 4(n); warp tile 32m x 32n; 2 CTAs/SM.
// ---------------------------------------------------------------------------
constexpr int A_PLANE = 5120;       // 64 rows * 80B
constexpr int B_PLANE = 10240;      // 128 rows * 80B
constexpr int STAGE = A_PLANE + B_PLANE;       // 15360
constexpr int NSTAGE = 4;
constexpr int V_OFF = STAGE * NSTAGE;          // 61440
constexpr int DEC_OFF = V_OFF + 4096;
constexpr int RED_OFF = DEC_OFF + 4096;
constexpr int SMEM_BYTES = RED_OFF + 4096;     // 73728

__device__ __forceinline__ void fill_slab(uint32_t sb, int st, int s,
                                          int row0, int n0, int tid) {
#pragma unroll
    for (int it = 0; it < 3; it++) {
        int idx = tid + it * 256;           // 0..767
        if (idx < 256) {
            int m = idx >> 2;
            int c = idx & 3;
            const __half* src = g_A + (size_t)(row0 + m) * HH + s * 32 + c * 8;
            uint32_t dst = sb + (uint32_t)(st * STAGE) + m * 80 + c * 16;
            cp_async16(dst, src);
        } else {
            int loc = idx - 256;
            int m = loc >> 2;
            int c = loc & 3;
            const __half* src = g_B + (size_t)(n0 + m) * HH + s * 32 + c * 8;
            uint32_t dst = sb + (uint32_t)(st * STAGE) + A_PLANE + m * 80 + c * 16;
            cp_async16(dst, src);
        }
    }
}

__global__ void __launch_bounds__(256, 2)
score_kernel(const float* __restrict__ vvec) {
    extern __shared__ char smem[];
    const uint32_t sb = smem_u32(smem);
    const int tid = threadIdx.x;
    const int warp = tid >> 5;
    const int lane = tid & 31;
    const int wm = warp >> 2;   // 0..1
    const int wn = warp & 3;    // 0..3
    const int row0 = blockIdx.x * 64;
    const int b = blockIdx.x >> 5;    // 32 CTAs per batch

    float* v_s = (float*)(smem + V_OFF);
    float* dec_s = (float*)(smem + DEC_OFF);
    for (int i = tid; i < 1024; i += 256) {
        v_s[i] = vvec[i];
        dec_s[i] = g_decfea[b * 1024 + i];
    }
    __syncthreads();

    const int a_row = wm * 32 + (lane & 15);                    // + mt*16
    const int a_col = ((lane >> 4) << 4);                       // 0 or 16 bytes
    const int b_row = wn * 32 + (((lane >> 4) & 1) << 3) + (lane & 7);  // + q*16
    const int b_col = (((lane >> 3) & 1) << 4);

    float msum[4];
#pragma unroll
    for (int i = 0; i < 4; i++) msum[i] = 0.f;

#pragma unroll 1
    for (int nc = 0; nc < 8; nc++) {
        const int n0 = nc * 128;
        float acc[2][4][4];
#pragma unroll
        for (int mt = 0; mt < 2; mt++)
#pragma unroll
            for (int nt = 0; nt < 4; nt++)
#pragma unroll
                for (int c = 0; c < 4; c++) acc[mt][nt][c] = 0.f;

        fill_slab(sb, 0, 0, row0, n0, tid);
        cp_commit();
        fill_slab(sb, 1, 1, row0, n0, tid);
        cp_commit();
        fill_slab(sb, 2, 2, row0, n0, tid);
        cp_commit();

        int st = 0;
#pragma unroll 1
        for (int s = 0; s < 32; s++) {
            if (s <= 29) {
                cp_wait<2>();
            } else if (s == 30) {
                cp_wait<1>();
            } else {
                cp_wait<0>();
            }
            __syncthreads();  // single barrier per slab

            if (s < 29) {
                fill_slab(sb, (st + 3) & 3, s + 3, row0, n0, tid);
                cp_commit();
            }

            const uint32_t abase = sb + (uint32_t)(st * STAGE);
            const uint32_t bbase = abase + (uint32_t)A_PLANE;
#pragma unroll
            for (int ks = 0; ks < 2; ks++) {
                uint32_t ah[2][4];
#pragma unroll
                for (int mt = 0; mt < 2; mt++) {
                    uint32_t ra = abase + (a_row + mt * 16) * 80 + a_col + ks * 32;
                    ldsm_x4(ra, ah[mt][0], ah[mt][1], ah[mt][2], ah[mt][3]);
                }
#pragma unroll
                for (int q = 0; q < 2; q++) {
                    uint32_t bm[2][2];
                    {
                        uint32_t rb = bbase + (b_row + q * 16) * 80 + b_col + ks * 32;
                        uint32_t r0, r1, r2, r3;
                        ldsm_x4(rb, r0, r1, r2, r3);
                        bm[0][0] = r0; bm[0][1] = r1;
                        bm[1][0] = r2; bm[1][1] = r3;
                    }
#pragma unroll
                    for (int mt = 0; mt < 2; mt++)
#pragma unroll
                        for (int j = 0; j < 2; j++)
                            mma_f32(acc[mt][2 * q + j], ah[mt], bm[j]);
                }
            }
            st = (st + 1) & 3;
        }

        // Epilogue: msum += v[d]*tanh(acc + dec[d])
#pragma unroll
        for (int nt = 0; nt < 4; nt++) {
#pragma unroll
            for (int j = 0; j < 2; j++) {
                int d = n0 + wn * 32 + nt * 8 + 2 * (lane & 3) + j;
                float vd = v_s[d];
                float dj = dec_s[d];
#pragma unroll
                for (int mt = 0; mt < 2; mt++) {
#pragma unroll
                    for (int h = 0; h < 2; h++) {
                        float x = acc[mt][nt][h * 2 + j] + dj;
                        msum[mt * 2 + h] += vd * fast_tanh(x);
                    }
                }
            }
        }
    }

    // Cross-warp reduction (64 rows x 16 partials)
    float* red = (float*)(smem + RED_OFF);
    __syncthreads();
#pragma unroll
    for (int mt = 0; mt < 2; mt++)
#pragma unroll
        for (int h = 0; h < 2; h++) {
            int m = wm * 32 + mt * 16 + h * 8 + (lane >> 2);
            red[m * 16 + wn * 4 + (lane & 3)] = msum[mt * 2 + h];
        }
    __syncthreads();
    if (tid < 64) {
        float sum = 0.f;
#pragma unroll
        for (int x = 0; x < 16; x++) sum += red[tid * 16 + x];
        g_scores[row0 + tid] = sum;
    }
}

// ---------------------------------------------------------------------------
// ct kernel with FUSED softmax, reading fp16 g_A.
// NOW 64-row chunks (grid 32 x BB = 1024 blocks) — R15 profile showed
// occupancy was grid-limited (40.7%) at only 54% DRAM.
// ---------------------------------------------------------------------------
__global__ void ct_softmax_kernel(float* __restrict__ out) {
    const int b = blockIdx.y;
    const int chunk = blockIdx.x;   // 0..31
    const int tid = threadIdx.x;    // 256
    __shared__ float sred[256];
    __shared__ float w_s[64];

    const float* sc = g_scores + b * TT;

    float vals[8];
    float mx = -INFINITY;
#pragma unroll
    for (int i = 0; i < 8; i++) {
        vals[i] = sc[tid + i * 256];
        mx = fmaxf(mx, vals[i]);
    }
    sred[tid] = mx;
    __syncthreads();
    for (int s = 128; s > 0; s >>= 1) {
        if (tid < s) sred[tid] = fmaxf(sred[tid], sred[tid + s]);
        __syncthreads();
    }
    mx = sred[0];
    __syncthreads();
    float sum = 0.f;
#pragma unroll
    for (int i = 0; i < 8; i++) sum += __expf(vals[i] - mx);
    sred[tid] = sum;
    __syncthreads();
    for (int s = 128; s > 0; s >>= 1) {
        if (tid < s) sred[tid] += sred[tid + s];
        __syncthreads();
    }
    const float inv = 1.0f / sred[0];

    const int t0 = chunk * 64;
    if (tid < 64) w_s[tid] = __expf(sc[t0 + tid] - mx) * inv;
    __syncthreads();

    const uint2* src =
        reinterpret_cast<const uint2*>(g_A + ((size_t)b * TT + t0) * HH);
    float acc[4] = {0.f, 0.f, 0.f, 0.f};
#pragma unroll 4
    for (int t = 0; t < 64; t++) {
        uint2 p = src[(size_t)t * 256 + tid];
        float at = w_s[t];
        float2 f0 = __half22float2(*reinterpret_cast<__half2*>(&p.x));
        float2 f1 = __half22float2(*reinterpret_cast<__half2*>(&p.y));
        acc[0] += at * f0.x;
        acc[1] += at * f0.y;
        acc[2] += at * f1.x;
        acc[3] += at * f1.y;
    }
    float* ctb = out + (size_t)b * HH + tid * 4;
    atomicAdd(ctb + 0, acc[0]);
    atomicAdd(ctb + 1, acc[1]);
    atomicAdd(ctb + 2, acc[2]);
    atomicAdd(ctb + 3, acc[3]);
}

// ---------------------------------------------------------------------------
extern "C" void kernel_launch(void* const* d_in, const int* in_sizes, int n_in,
                              void* d_out, int out_size) {
    const float* s_t    = (const float*)d_in[0];
    const float* prev_s = (const float*)d_in[1];
    const float* W_prev = (const float*)d_in[2];
    const float* W_s    = (const float*)d_in[3];
    const float* b_s    = (const float*)d_in[4];
    const float* v      = (const float*)d_in[5];
    float* out = (float*)d_out;

    static bool once = false;
    if (!once) {
        cudaFuncSetAttribute(score_kernel,
                             cudaFuncAttributeMaxDynamicSharedMemorySize, SMEM_BYTES);
        once = true;
    }

    __half *gA, *gB;
    cudaGetSymbolAddress((void**)&gA, g_A);
    cudaGetSymbolAddress((void**)&gB, g_B);

    init_kernel<<<64, 256>>>(s_t, out);
    conv_b_kernel<<<512, 256>>>(W_prev, gB);
    dec_fea_kernel<<<HH / 8, 256>>>(s_t, W_s, b_s);
    conv_half_copy_kernel<<<32768, 256>>>(prev_s, gA, out);
    score_kernel<<<(BB * TT) / 64, 256, SMEM_BYTES>>>(v);
    dim3 gt(32, BB);
    ct_softmax_kernel<<<gt, 256>>>(out);
}